// round 1
// baseline (speedup 1.0000x reference)
#include <cuda_runtime.h>
#include <math.h>
#include <stdint.h>

#define N_PIX   (512 * 512)
#define BM      16
#define NTHR    256
#define SH_STRIDE 520   // padded row stride (floats) for h1/h2 tiles

// ---------------------------------------------------------------------------
// Accurate sin/cos independent of -use_fast_math: Cody-Waite reduction in
// double (k up to ~65536, reduction error ~1e-12), Cephes fp32 polynomials.
// cos(x) = sin(x + pi/2) -> quadrant shift.
// ---------------------------------------------------------------------------
__device__ __forceinline__ float trig_eval(float x, int cos_flag) {
    double d  = (double)x * 0.63661977236758134308;     // x * 2/pi
    int    ki = __double2int_rn(d);
    float  rf = (float)((double)x - (double)ki * 1.57079632679489661923);
    int    q  = (ki + cos_flag) & 3;
    float  z  = rf * rf;
    // sin poly on [-pi/4, pi/4]
    float s = ((-1.9515295891e-4f * z + 8.3321608736e-3f) * z - 1.6666654611e-1f)
                  * z * rf + rf;
    // cos poly on [-pi/4, pi/4]
    float c = ((2.443315711809948e-5f * z - 1.388731625493765e-3f) * z
                  + 4.166664568298827e-2f) * z * z - 0.5f * z + 1.0f;
    float res = (q & 1) ? c : s;
    return (q & 2) ? -res : res;
}

__device__ float g_b1eff[512];

// ---------------------------------------------------------------------------
// Kernel A: time branch. 1 block, 256 threads.
// phi_t = W2p^T relu(W1p^T posenc_t(idx/300) + b1p) + b2p
// g_b1eff[j] = b1f[j] + sum_k phi_t[k] * W1f[(40+k)*512 + j]
// ---------------------------------------------------------------------------
__global__ void nivr_setup_kernel(const float* __restrict__ W1p,
                                  const float* __restrict__ b1p,
                                  const float* __restrict__ W2p,
                                  const float* __restrict__ b2p,
                                  const float* __restrict__ W1f,
                                  const float* __restrict__ b1f,
                                  const int*   __restrict__ idx_p) {
    __shared__ float sr[32];
    __shared__ float sh[256];
    __shared__ float sphi[128];
    const int tid = threadIdx.x;

    float t = (float)(*idx_p) / 300.0f;
    if (tid < 32) {
        int   l   = tid & 15;
        // (t * 2^l) exact scaling, then * pi_f: one rounding (matches ref order)
        float ang = (t * (float)(1 << l)) * 3.14159265358979323846f;
        sr[tid] = trig_eval(ang, tid >= 16);
    }
    __syncthreads();

    {   // h = relu(r @ W1p + b1p), W1p [32, 256]
        float acc = b1p[tid];
        #pragma unroll
        for (int k = 0; k < 32; k++)
            acc = fmaf(sr[k], W1p[k * 256 + tid], acc);
        sh[tid] = fmaxf(acc, 0.0f);
    }
    __syncthreads();

    if (tid < 128) {   // phi = h @ W2p + b2p, W2p [256, 128]
        float acc = b2p[tid];
        #pragma unroll 4
        for (int k = 0; k < 256; k++)
            acc = fmaf(sh[k], W2p[k * 128 + tid], acc);
        sphi[tid] = acc;
    }
    __syncthreads();

    for (int j = tid; j < 512; j += NTHR) {   // fold phi into layer-1 bias
        float acc = b1f[j];
        #pragma unroll 4
        for (int k = 0; k < 128; k++)
            acc = fmaf(sphi[k], W1f[(40 + k) * 512 + j], acc);
        g_b1eff[j] = acc;
    }
}

// ---------------------------------------------------------------------------
// Kernel B: main MLP over pixels. BM=16 pixels per block, 256 threads.
// Each thread owns output columns (2*tid, 2*tid+1) for all 16 pixels.
// ---------------------------------------------------------------------------
__global__ __launch_bounds__(NTHR, 2)
void nivr_main_kernel(const float* __restrict__ coords,
                      const float* __restrict__ W1f,
                      const float* __restrict__ W2f,
                      const float* __restrict__ b2f,
                      const float* __restrict__ W3f,
                      const float* __restrict__ b3f,
                      float* __restrict__ out) {
    extern __shared__ float smem[];
    float* sC  = smem;                      // [BM * 40]
    float* sH1 = sC  + BM * 40;             // [BM * SH_STRIDE]
    float* sH2 = sH1 + BM * SH_STRIDE;      // [BM * SH_STRIDE]
    float* sW3 = sH2 + BM * SH_STRIDE;      // [512 * 3]
    float* sB1 = sW3 + 512 * 3;             // [512]

    const int tid  = threadIdx.x;
    const int base = blockIdx.x * BM;
    const int j0   = tid * 2;

    for (int i = tid; i < 512 * 3; i += NTHR) sW3[i] = W3f[i];
    for (int i = tid; i < 512; i += NTHR)     sB1[i] = g_b1eff[i];

    // posenc: sC[p][f], f = [sin_x(10), cos_x(10), sin_y(10), cos_y(10)]
    for (int v = tid; v < BM * 40; v += NTHR) {
        int   p     = v / 40;
        int   f     = v % 40;
        int   fl    = f % 20;
        float coord = coords[(base + p) * 2 + (f >= 20)];
        // ((c/512) * 2^l) exact, * pi_f one rounding -> matches reference
        float ang = ((coord * (1.0f / 512.0f)) * (float)(1 << (fl % 10)))
                        * 3.14159265358979323846f;
        sC[p * 40 + f] = trig_eval(ang, fl >= 10);
    }
    __syncthreads();

    // ---- layer 1: h1 = relu(c @ W1f[:40,:] + b1eff) --------------------
    {
        float2 acc[BM];
        float2 binit = make_float2(sB1[j0], sB1[j0 + 1]);
        #pragma unroll
        for (int p = 0; p < BM; p++) acc[p] = binit;

        #pragma unroll 4
        for (int k = 0; k < 40; k++) {
            float2 w = *(const float2*)&W1f[k * 512 + j0];
            #pragma unroll
            for (int p = 0; p < BM; p++) {
                float cv = sC[p * 40 + k];
                acc[p].x = fmaf(cv, w.x, acc[p].x);
                acc[p].y = fmaf(cv, w.y, acc[p].y);
            }
        }
        #pragma unroll
        for (int p = 0; p < BM; p++) {
            float2 r = make_float2(fmaxf(acc[p].x, 0.0f), fmaxf(acc[p].y, 0.0f));
            *(float2*)&sH1[p * SH_STRIDE + j0] = r;
        }
    }
    __syncthreads();

    // ---- layer 2: h2 = relu(h1 @ W2f + b2f) ----------------------------
    {
        float2 acc[BM];
        float2 binit = *(const float2*)&b2f[j0];
        #pragma unroll
        for (int p = 0; p < BM; p++) acc[p] = binit;

        #pragma unroll 2
        for (int kk = 0; kk < 512; kk += 4) {
            const float* wb = &W2f[kk * 512 + j0];
            float2 w0 = *(const float2*)(wb);
            float2 w1 = *(const float2*)(wb + 512);
            float2 w2 = *(const float2*)(wb + 1024);
            float2 w3 = *(const float2*)(wb + 1536);
            #pragma unroll
            for (int p = 0; p < BM; p++) {
                float4 h = *(const float4*)&sH1[p * SH_STRIDE + kk];
                acc[p].x = fmaf(h.x, w0.x, acc[p].x);
                acc[p].y = fmaf(h.x, w0.y, acc[p].y);
                acc[p].x = fmaf(h.y, w1.x, acc[p].x);
                acc[p].y = fmaf(h.y, w1.y, acc[p].y);
                acc[p].x = fmaf(h.z, w2.x, acc[p].x);
                acc[p].y = fmaf(h.z, w2.y, acc[p].y);
                acc[p].x = fmaf(h.w, w3.x, acc[p].x);
                acc[p].y = fmaf(h.w, w3.y, acc[p].y);
            }
        }
        #pragma unroll
        for (int p = 0; p < BM; p++) {
            float2 r = make_float2(fmaxf(acc[p].x, 0.0f), fmaxf(acc[p].y, 0.0f));
            *(float2*)&sH2[p * SH_STRIDE + j0] = r;
        }
    }
    __syncthreads();

    // ---- layer 3: rgb = h2 @ W3f + b3f ---------------------------------
    // 48 outputs, 4-way split-k: 192 threads (warps 0..5 fully active).
    if (tid < 192) {
        int g    = tid >> 2;        // 0..47  -> (pixel, channel)
        int part = tid & 3;         // k-range quarter
        int p    = g / 3;
        int ch   = g % 3;
        float acc = 0.0f;
        int k0 = part * 128;
        #pragma unroll 4
        for (int k = k0; k < k0 + 128; k++)
            acc = fmaf(sH2[p * SH_STRIDE + k], sW3[k * 3 + ch], acc);
        acc += __shfl_xor_sync(0xffffffffu, acc, 1);
        acc += __shfl_xor_sync(0xffffffffu, acc, 2);
        if (part == 0)
            out[ch * N_PIX + base + p] = acc + b3f[ch];
    }
}

// ---------------------------------------------------------------------------
extern "C" void kernel_launch(void* const* d_in, const int* in_sizes, int n_in,
                              void* d_out, int out_size) {
    const float* coords = (const float*)d_in[0];
    const float* W1p    = (const float*)d_in[1];
    const float* b1p    = (const float*)d_in[2];
    const float* W2p    = (const float*)d_in[3];
    const float* b2p    = (const float*)d_in[4];
    const float* W1f    = (const float*)d_in[5];
    const float* b1f    = (const float*)d_in[6];
    const float* W2f    = (const float*)d_in[7];
    const float* b2f    = (const float*)d_in[8];
    const float* W3f    = (const float*)d_in[9];
    const float* b3f    = (const float*)d_in[10];
    const int*   idx    = (const int*)d_in[11];
    float*       out    = (float*)d_out;

    const int smem_bytes =
        (BM * 40 + 2 * BM * SH_STRIDE + 512 * 3 + 512) * (int)sizeof(float);

    // > 48KB dynamic smem requires opt-in (host-side attr, not captured; idempotent)
    cudaFuncSetAttribute(nivr_main_kernel,
                         cudaFuncAttributeMaxDynamicSharedMemorySize, smem_bytes);

    nivr_setup_kernel<<<1, NTHR>>>(W1p, b1p, W2p, b2p, W1f, b1f, idx);
    nivr_main_kernel<<<N_PIX / BM, NTHR, smem_bytes>>>(coords, W1f, W2f, b2f,
                                                       W3f, b3f, out);
}